// round 4
// baseline (speedup 1.0000x reference)
#include <cuda_runtime.h>
#include <cuda_fp16.h>
#include <cstdint>

#define E_NUM 32
#define DK 1024
#define DN 1024
#define BM 128
#define BN 128
#define KC 64            /* fp16 per K-chunk = 128 bytes/row */
#define NCHUNK (DK / KC) /* 16 */
#define STAGES 3
#define MT_CAP 1152
#define TMAX 131072LL

/* ---------------- scratch (device globals; no allocation APIs) -------------- */
static __device__ __align__(1024) __half g_Ah[TMAX * DK];                   /* 256 MB */
static __device__ __align__(1024) __half g_Wh[(long long)E_NUM * DN * DK];  /* 64 MB  */
static __device__ int g_tile_expert[MT_CAP];
static __device__ int g_tile_row[MT_CAP];
static __device__ int g_tile_nrows[MT_CAP];
static __device__ int g_num_mtiles;

/* ---------------- helpers ---------------- */
static __device__ __forceinline__ uint32_t smem_u32(const void* p) {
    uint32_t a;
    asm("{ .reg .u64 t; cvta.to.shared.u64 t, %1; cvt.u32.u64 %0, t; }" : "=r"(a) : "l"(p));
    return a;
}
static __device__ __forceinline__ void cp16(uint32_t dst, const void* src, int src_size) {
    asm volatile("cp.async.cg.shared.global [%0], [%1], 16, %2;\n"
                 :: "r"(dst), "l"(src), "r"(src_size));
}
#define CP_COMMIT()  asm volatile("cp.async.commit_group;\n" ::: "memory")

#define LDSM_X4(r0, r1, r2, r3, addr) \
    asm volatile("ldmatrix.sync.aligned.m8n8.x4.shared.b16 {%0,%1,%2,%3}, [%4];" \
                 : "=r"(r0), "=r"(r1), "=r"(r2), "=r"(r3) : "r"(addr))

#define MMA16816(c0, c1, c2, c3, a0, a1, a2, a3, b0, b1) \
    asm volatile("mma.sync.aligned.m16n8k16.row.col.f32.f16.f16.f32 " \
                 "{%0,%1,%2,%3}, {%4,%5,%6,%7}, {%8,%9}, {%0,%1,%2,%3};" \
                 : "+f"(c0), "+f"(c1), "+f"(c2), "+f"(c3) \
                 : "r"(a0), "r"(a1), "r"(a2), "r"(a3), "r"(b0), "r"(b1))

/* ---------------- pre-pass kernels ---------------- */
__global__ void cvtA_kernel(const float4* __restrict__ src, long long n4) {
    long long i = (long long)blockIdx.x * blockDim.x + threadIdx.x;
    long long stride = (long long)gridDim.x * blockDim.x;
    uint2* dst = reinterpret_cast<uint2*>(g_Ah);
    for (; i < n4; i += stride) {
        float4 v = src[i];
        __half2 h0 = __floats2half2_rn(v.x, v.y);
        __half2 h1 = __floats2half2_rn(v.z, v.w);
        uint2 u;
        u.x = *reinterpret_cast<uint32_t*>(&h0);
        u.y = *reinterpret_cast<uint32_t*>(&h1);
        dst[i] = u;
    }
}
__global__ void cvtW_kernel(const float4* __restrict__ src, long long n4) {
    long long i = (long long)blockIdx.x * blockDim.x + threadIdx.x;
    long long stride = (long long)gridDim.x * blockDim.x;
    uint2* dst = reinterpret_cast<uint2*>(g_Wh);
    for (; i < n4; i += stride) {
        float4 v = src[i];
        __half2 h0 = __floats2half2_rn(v.x, v.y);
        __half2 h1 = __floats2half2_rn(v.z, v.w);
        uint2 u;
        u.x = *reinterpret_cast<uint32_t*>(&h0);
        u.y = *reinterpret_cast<uint32_t*>(&h1);
        dst[i] = u;
    }
}

/* Build tile table. Handles expert_frequency delivered as int32 OR int64. */
__global__ void build_tiles_kernel(const int* __restrict__ ef, int T_tokens) {
    if (threadIdx.x != 0 || blockIdx.x != 0) return;
    long long s = 0;
    for (int i = 0; i < E_NUM; i++) s += ef[i];
    bool is64 = (s != (long long)T_tokens);
    long long off = 0;
    int t = 0;
    for (int e = 0; e < E_NUM; e++) {
        long long c;
        if (is64)
            c = (long long)(unsigned)ef[2 * e] | ((long long)ef[2 * e + 1] << 32);
        else
            c = ef[e];
        for (long long m = 0; m < c; m += BM) {
            long long rem = c - m;
            g_tile_expert[t] = e;
            g_tile_row[t]    = (int)(off + m);
            g_tile_nrows[t]  = (int)(rem < BM ? rem : BM);
            t++;
        }
        off += c;
    }
    g_num_mtiles = t;
}

/* ---------------- main grouped-GEMM kernel (mma.sync fp16) ----------------
   CTA tile 128x128, 4 warps (2m x 2n) -> warp tile 64x64. K-chunk 64,
   3-stage cp.async, double-buffered ldmatrix fragments. 2 CTAs/SM so one
   CTA's MMAs cover the other's barrier/LDSM phases.                          */

#define A_STAGE 16384                   /* 128 rows x 128B */
#define B_STAGE 16384
#define STAGE_BYTES (A_STAGE + B_STAGE) /* 32KB */
#define SMEM_TOTAL  (STAGES * STAGE_BYTES) /* 96KB */

static __device__ __forceinline__ void load_stage(
    int c, int slot, uint32_t smem_base,
    const __half* __restrict__ gA, const __half* __restrict__ gB,
    int a_sz, int tid)
{
    uint32_t sA = smem_base + (uint32_t)slot * STAGE_BYTES;
    uint32_t sB = sA + A_STAGE;
    const int row = tid;                 /* 128 threads, one full row each */
    const uint32_t xorv = (uint32_t)(row & 7) * 16u;
    uint32_t dstA = sA + (uint32_t)row * 128u;
    uint32_t dstB = sB + (uint32_t)row * 128u;
    const char* srcA = (const char*)(gA + (size_t)row * DK + (size_t)c * KC);
    const char* srcB = (const char*)(gB + (size_t)row * DK + (size_t)c * KC);
#pragma unroll
    for (int j = 0; j < 8; j++) {
        uint32_t col = ((uint32_t)j * 16u) ^ xorv;
        cp16(dstA + col, srcA + j * 16, a_sz);
        cp16(dstB + col, srcB + j * 16, 16);
    }
    CP_COMMIT();
}

__global__ void __launch_bounds__(128, 2) gemm_kernel(
    const float* __restrict__ bias, float* __restrict__ out, int T_tokens)
{
    extern __shared__ __align__(1024) char smem[];
    const int nt = blockIdx.x;           /* fast dim: 8 N-tiles co-resident for A reuse in L2 */
    const int mt = blockIdx.y;
    if (mt >= g_num_mtiles) return;

    const int e     = g_tile_expert[mt];
    const int row0  = g_tile_row[mt];
    const int nrows = g_tile_nrows[mt];

    const uint32_t smem_base = smem_u32(smem);
    const int tid  = threadIdx.x;
    const int lane = tid & 31;
    const int wid  = tid >> 5;
    const int warp_m = wid >> 1;         /* 0..1 -> 64 rows each */
    const int warp_n = wid & 1;          /* 0..1 -> 64 cols each */

    /* global load setup */
    const int a_sz = (row0 + tid < T_tokens) ? 16 : 0;
    const __half* gA = g_Ah + (size_t)row0 * DK;
    const __half* gB = g_Wh + ((size_t)e * DN + (size_t)nt * BN) * DK;

    /* ldmatrix per-lane address components */
    uint32_t aOff[4], aXor[4];
#pragma unroll
    for (int mf = 0; mf < 4; mf++) {
        int r = warp_m * 64 + mf * 16 + (lane & 15);
        aOff[mf] = (uint32_t)r * 128u;
        aXor[mf] = (uint32_t)(r & 7) * 16u;
    }
    const uint32_t aHi = (uint32_t)((lane >> 4) & 1) * 16u;

    uint32_t bOff[4], bXor[4];
#pragma unroll
    for (int g = 0; g < 4; g++) {
        int r = warp_n * 64 + g * 16 + (lane & 7) + (((lane >> 4) & 1) << 3);
        bOff[g] = (uint32_t)r * 128u;
        bXor[g] = (uint32_t)(r & 7) * 16u;
    }
    const uint32_t bHi = (uint32_t)((lane >> 3) & 1) * 16u;

    float acc[4][8][4];
#pragma unroll
    for (int mf = 0; mf < 4; mf++)
#pragma unroll
        for (int nf = 0; nf < 8; nf++)
#pragma unroll
            for (int k = 0; k < 4; k++) acc[mf][nf][k] = 0.0f;

    uint32_t af[2][4][4];   /* [buf][mf][reg] */
    uint32_t bf[2][4][4];   /* [buf][g][reg]  */

    /* prologue loads */
    load_stage(0, 0, smem_base, gA, gB, a_sz, tid);
    load_stage(1, 1, smem_base, gA, gB, a_sz, tid);

#pragma unroll 1
    for (int c = 0; c < NCHUNK; c++) {
        if (c < NCHUNK - 1) asm volatile("cp.async.wait_group 1;" ::: "memory");
        else                asm volatile("cp.async.wait_group 0;" ::: "memory");
        __syncthreads();

        const uint32_t sA = smem_base + (uint32_t)(c % STAGES) * STAGE_BYTES;
        const uint32_t sB = sA + A_STAGE;

        /* load fragments for ks=0 into buffer 0 */
#pragma unroll
        for (int mf = 0; mf < 4; mf++) {
            uint32_t addr = sA + aOff[mf] + ((0u + aHi) ^ aXor[mf]);
            LDSM_X4(af[0][mf][0], af[0][mf][1], af[0][mf][2], af[0][mf][3], addr);
        }
#pragma unroll
        for (int g = 0; g < 4; g++) {
            uint32_t addr = sB + bOff[g] + ((0u + bHi) ^ bXor[g]);
            LDSM_X4(bf[0][g][0], bf[0][g][1], bf[0][g][2], bf[0][g][3], addr);
        }

        /* issue next stage's global loads behind the critical LDSMs */
        if (c + 2 < NCHUNK)
            load_stage(c + 2, (c + 2) % STAGES, smem_base, gA, gB, a_sz, tid);

#pragma unroll
        for (int ks = 0; ks < 4; ks++) {
            const int cur = ks & 1;
            const int nxt = cur ^ 1;
            if (ks < 3) {
                const uint32_t kb = (uint32_t)(ks + 1) * 32u;
#pragma unroll
                for (int mf = 0; mf < 4; mf++) {
                    uint32_t addr = sA + aOff[mf] + ((kb + aHi) ^ aXor[mf]);
                    LDSM_X4(af[nxt][mf][0], af[nxt][mf][1], af[nxt][mf][2], af[nxt][mf][3], addr);
                }
#pragma unroll
                for (int g = 0; g < 4; g++) {
                    uint32_t addr = sB + bOff[g] + ((kb + bHi) ^ bXor[g]);
                    LDSM_X4(bf[nxt][g][0], bf[nxt][g][1], bf[nxt][g][2], bf[nxt][g][3], addr);
                }
            }
#pragma unroll
            for (int mf = 0; mf < 4; mf++) {
#pragma unroll
                for (int nf = 0; nf < 8; nf++) {
                    const int g  = nf >> 1;
                    const int hi = (nf & 1) * 2;
                    MMA16816(acc[mf][nf][0], acc[mf][nf][1], acc[mf][nf][2], acc[mf][nf][3],
                             af[cur][mf][0], af[cur][mf][1], af[cur][mf][2], af[cur][mf][3],
                             bf[cur][g][hi], bf[cur][g][hi + 1]);
                }
            }
        }
    }

    /* epilogue: out = acc + bias */
    const int colBase = nt * BN + warp_n * 64 + (lane & 3) * 2;
    const float* brow = bias + (size_t)e * DN;
#pragma unroll
    for (int mf = 0; mf < 4; mf++) {
#pragma unroll
        for (int half = 0; half < 2; half++) {
            const int r = warp_m * 64 + mf * 16 + (lane >> 2) + half * 8;
            if (r < nrows) {
                float* orow = out + (size_t)(row0 + r) * DN;
#pragma unroll
                for (int nf = 0; nf < 8; nf++) {
                    const int col = colBase + nf * 8;
                    float2 v;
                    v.x = acc[mf][nf][half * 2 + 0] + brow[col];
                    v.y = acc[mf][nf][half * 2 + 1] + brow[col + 1];
                    *(float2*)(orow + col) = v;
                }
            }
        }
    }
}

/* ---------------- host launcher ---------------- */
extern "C" void kernel_launch(void* const* d_in, const int* in_sizes, int n_in,
                              void* d_out, int out_size)
{
    const float* x    = (const float*)d_in[0];
    const int*   ef   = (const int*)d_in[1];
    const float* w    = (const float*)d_in[2];
    const float* bias = (const float*)d_in[3];
    float* out = (float*)d_out;

    const long long T = (long long)in_sizes[0] / DK;

    const long long nA4 = T * DK / 4;
    cvtA_kernel<<<4096, 256>>>((const float4*)x, nA4);
    const long long nW4 = (long long)E_NUM * DN * DK / 4;
    cvtW_kernel<<<2048, 256>>>((const float4*)w, nW4);
    build_tiles_kernel<<<1, 32>>>(ef, (int)T);

    cudaFuncSetAttribute(gemm_kernel, cudaFuncAttributeMaxDynamicSharedMemorySize, SMEM_TOTAL);

    const int mt_max = (int)((T + BM - 1) / BM) + E_NUM;   /* ~1056 */
    dim3 grid(DN / BN, (unsigned)mt_max);                  /* (8, ~1056) */
    gemm_kernel<<<grid, 128, SMEM_TOTAL>>>(bias, out, (int)T);
}

// round 5
// speedup vs baseline: 1.2877x; 1.2877x over previous
#include <cuda_runtime.h>
#include <cuda_fp16.h>
#include <cstdint>

#define E_NUM 32
#define DK 1024
#define DN 1024
#define BM 128
#define BN 128
#define KC 64            /* fp16 per K-chunk = 128 bytes/row */
#define NCHUNK (DK / KC) /* 16 */
#define STAGES 3
#define MT_CAP 1152
#define TMAX 131072LL

/* ---------------- scratch (device globals; no allocation APIs) -------------- */
static __device__ __align__(1024) __half g_Ah[TMAX * DK];                   /* 256 MB */
static __device__ __align__(1024) __half g_Wh[(long long)E_NUM * DN * DK];  /* 64 MB  */
static __device__ int g_tile_expert[MT_CAP];
static __device__ int g_tile_row[MT_CAP];
static __device__ int g_tile_nrows[MT_CAP];
static __device__ int g_num_mtiles;

/* ---------------- helpers ---------------- */
static __device__ __forceinline__ uint32_t smem_u32(const void* p) {
    uint32_t a;
    asm("{ .reg .u64 t; cvta.to.shared.u64 t, %1; cvt.u32.u64 %0, t; }" : "=r"(a) : "l"(p));
    return a;
}
static __device__ __forceinline__ void cp16(uint32_t dst, const void* src, int src_size) {
    asm volatile("cp.async.cg.shared.global [%0], [%1], 16, %2;\n"
                 :: "r"(dst), "l"(src), "r"(src_size));
}
#define CP_COMMIT()  asm volatile("cp.async.commit_group;\n" ::: "memory")

#define LDSM_X4(r0, r1, r2, r3, addr) \
    asm volatile("ldmatrix.sync.aligned.m8n8.x4.shared.b16 {%0,%1,%2,%3}, [%4];" \
                 : "=r"(r0), "=r"(r1), "=r"(r2), "=r"(r3) : "r"(addr))

#define MMA16816(c0, c1, c2, c3, a0, a1, a2, a3, b0, b1) \
    asm volatile("mma.sync.aligned.m16n8k16.row.col.f32.f16.f16.f32 " \
                 "{%0,%1,%2,%3}, {%4,%5,%6,%7}, {%8,%9}, {%0,%1,%2,%3};" \
                 : "+f"(c0), "+f"(c1), "+f"(c2), "+f"(c3) \
                 : "r"(a0), "r"(a1), "r"(a2), "r"(a3), "r"(b0), "r"(b1))

/* ---------------- fused fp32->fp16 conversion (W then A, one launch) -------- */
__global__ void cvt_all_kernel(const float4* __restrict__ srcW,
                               const float4* __restrict__ srcA,
                               long long nW4, long long nA4) {
    long long i = (long long)blockIdx.x * blockDim.x + threadIdx.x;
    long long stride = (long long)gridDim.x * blockDim.x;
    uint2* dstW = reinterpret_cast<uint2*>(g_Wh);
    uint2* dstA = reinterpret_cast<uint2*>(g_Ah);
    const long long ntot = nW4 + nA4;
    for (; i < ntot; i += stride) {
        const bool isW = (i < nW4);
        const long long j = isW ? i : (i - nW4);
        float4 v = isW ? srcW[j] : srcA[j];
        __half2 h0 = __floats2half2_rn(v.x, v.y);
        __half2 h1 = __floats2half2_rn(v.z, v.w);
        uint2 u;
        u.x = *reinterpret_cast<uint32_t*>(&h0);
        u.y = *reinterpret_cast<uint32_t*>(&h1);
        if (isW) dstW[j] = u; else dstA[j] = u;
    }
}

/* Build tile table. Handles expert_frequency delivered as int32 OR int64. */
__global__ void build_tiles_kernel(const int* __restrict__ ef, int T_tokens) {
    if (threadIdx.x != 0 || blockIdx.x != 0) return;
    long long s = 0;
    for (int i = 0; i < E_NUM; i++) s += ef[i];
    bool is64 = (s != (long long)T_tokens);
    long long off = 0;
    int t = 0;
    for (int e = 0; e < E_NUM; e++) {
        long long c;
        if (is64)
            c = (long long)(unsigned)ef[2 * e] | ((long long)ef[2 * e + 1] << 32);
        else
            c = ef[e];
        for (long long m = 0; m < c; m += BM) {
            long long rem = c - m;
            g_tile_expert[t] = e;
            g_tile_row[t]    = (int)(off + m);
            g_tile_nrows[t]  = (int)(rem < BM ? rem : BM);
            t++;
        }
        off += c;
    }
    g_num_mtiles = t;
}

/* ---------------- main grouped-GEMM kernel (mma.sync fp16) ----------------
   Exact R2 config: CTA 128x128, 8 warps (4m x 2n), warp tile 32x64,
   K-chunk 64, 3-stage cp.async, 2 CTAs/SM. NEW: warp-phase skew — warps
   4..7 run the ks loop rotated by 2 so each SMSP holds one warp of each
   phase (SMSP = wid%4; pairs {0,4},{1,5},...), overlapping LDSM and MMA
   bursts deterministically.                                                 */

#define STAGE_BYTES 32768              /* A 16KB + B 16KB */
#define SMEM_TOTAL  (STAGES * STAGE_BYTES)

static __device__ __forceinline__ void load_stage(
    int c, int slot, uint32_t smem_base,
    const __half* __restrict__ gA, const __half* __restrict__ gB,
    int a_sz, int tid)
{
    const int row  = tid >> 1;
    const int j0   = (tid & 1) * 4;
    const uint32_t xorv = (uint32_t)(row & 7) * 16u;
    uint32_t sA = smem_base + (uint32_t)slot * STAGE_BYTES + (uint32_t)row * 128u;
    uint32_t sB = sA + 16384u;
    const char* srcA = (const char*)(gA + (size_t)row * DK + (size_t)c * KC) + j0 * 16;
    const char* srcB = (const char*)(gB + (size_t)row * DK + (size_t)c * KC) + j0 * 16;
#pragma unroll
    for (int j = 0; j < 4; j++) {
        uint32_t col = ((uint32_t)(j0 + j) * 16u) ^ xorv;
        cp16(sA + col, srcA + j * 16, a_sz);
        cp16(sB + col, srcB + j * 16, 16);
    }
    CP_COMMIT();
}

__global__ void __launch_bounds__(256, 2) gemm_kernel(
    const float* __restrict__ bias, float* __restrict__ out, int T_tokens)
{
    extern __shared__ __align__(1024) char smem[];
    const int nt = blockIdx.x;           /* fast dim: 8 N-tiles co-resident for A reuse in L2 */
    const int mt = blockIdx.y;
    if (mt >= g_num_mtiles) return;

    const int e     = g_tile_expert[mt];
    const int row0  = g_tile_row[mt];
    const int nrows = g_tile_nrows[mt];

    const uint32_t smem_base = smem_u32(smem);
    const int tid  = threadIdx.x;
    const int lane = tid & 31;
    const int wid  = tid >> 5;
    const int warp_m = wid >> 1;         /* 0..3 */
    const int warp_n = wid & 1;          /* 0..1 */
    const uint32_t ksrot = (uint32_t)((wid >> 2) & 1) << 1;  /* phase skew per SMSP-sibling */

    /* global load setup */
    const int arow = tid >> 1;
    const int a_sz = (row0 + arow < T_tokens) ? 16 : 0;
    const __half* gA = g_Ah + (size_t)row0 * DK;
    const __half* gB = g_Wh + ((size_t)e * DN + (size_t)nt * BN) * DK;

    /* ldmatrix per-lane address components */
    uint32_t aRow[2], aXor[2];
#pragma unroll
    for (int mf = 0; mf < 2; mf++) {
        int r = warp_m * 32 + mf * 16 + (lane & 15);
        aRow[mf] = (uint32_t)r * 128u;
        aXor[mf] = (uint32_t)(r & 7) * 16u;
    }
    const uint32_t aHi = (uint32_t)((lane >> 4) & 1) * 16u;

    uint32_t bRow[4], bXor[4];
#pragma unroll
    for (int g = 0; g < 4; g++) {
        int r = warp_n * 64 + g * 16 + (lane & 7) + (((lane >> 4) & 1) << 3);
        bRow[g] = (uint32_t)r * 128u;
        bXor[g] = (uint32_t)(r & 7) * 16u;
    }
    const uint32_t bHi = (uint32_t)((lane >> 3) & 1) * 16u;

    float acc[2][8][4];
#pragma unroll
    for (int mf = 0; mf < 2; mf++)
#pragma unroll
        for (int nf = 0; nf < 8; nf++)
#pragma unroll
            for (int k = 0; k < 4; k++) acc[mf][nf][k] = 0.0f;

    /* prologue */
    load_stage(0, 0, smem_base, gA, gB, a_sz, tid);
    load_stage(1, 1, smem_base, gA, gB, a_sz, tid);

#pragma unroll 1
    for (int c = 0; c < NCHUNK; c++) {
        if (c < NCHUNK - 1) asm volatile("cp.async.wait_group 1;" ::: "memory");
        else                asm volatile("cp.async.wait_group 0;" ::: "memory");
        __syncthreads();

        if (c + 2 < NCHUNK) {
            load_stage(c + 2, (c + 2) % STAGES, smem_base, gA, gB, a_sz, tid);
        }

        const uint32_t sA = smem_base + (uint32_t)(c % STAGES) * STAGE_BYTES;
        const uint32_t sB = sA + 16384u;

#pragma unroll
        for (int ks = 0; ks < 4; ks++) {
            const uint32_t kb = ((uint32_t)ks ^ ksrot) * 32u;   /* warp-phase skew */
            uint32_t a[2][4];
#pragma unroll
            for (int mf = 0; mf < 2; mf++) {
                uint32_t addr = sA + aRow[mf] + ((kb + aHi) ^ aXor[mf]);
                LDSM_X4(a[mf][0], a[mf][1], a[mf][2], a[mf][3], addr);
            }
            uint32_t b[4][4];
#pragma unroll
            for (int g = 0; g < 4; g++) {
                uint32_t addr = sB + bRow[g] + ((kb + bHi) ^ bXor[g]);
                LDSM_X4(b[g][0], b[g][1], b[g][2], b[g][3], addr);
            }
#pragma unroll
            for (int mf = 0; mf < 2; mf++) {
#pragma unroll
                for (int nf = 0; nf < 8; nf++) {
                    const int g  = nf >> 1;
                    const int hi = (nf & 1) * 2;
                    MMA16816(acc[mf][nf][0], acc[mf][nf][1], acc[mf][nf][2], acc[mf][nf][3],
                             a[mf][0], a[mf][1], a[mf][2], a[mf][3],
                             b[g][hi], b[g][hi + 1]);
                }
            }
        }
    }

    /* epilogue: out = acc + bias */
    const int colBase = nt * BN + warp_n * 64 + (lane & 3) * 2;
    const float* brow = bias + (size_t)e * DN;
#pragma unroll
    for (int mf = 0; mf < 2; mf++) {
#pragma unroll
        for (int half = 0; half < 2; half++) {
            const int r = warp_m * 32 + mf * 16 + (lane >> 2) + half * 8;
            if (r < nrows) {
                float* orow = out + (size_t)(row0 + r) * DN;
#pragma unroll
                for (int nf = 0; nf < 8; nf++) {
                    const int col = colBase + nf * 8;
                    float2 v;
                    v.x = acc[mf][nf][half * 2 + 0] + brow[col];
                    v.y = acc[mf][nf][half * 2 + 1] + brow[col + 1];
                    *(float2*)(orow + col) = v;
                }
            }
        }
    }
}

/* ---------------- host launcher ---------------- */
extern "C" void kernel_launch(void* const* d_in, const int* in_sizes, int n_in,
                              void* d_out, int out_size)
{
    const float* x    = (const float*)d_in[0];
    const int*   ef   = (const int*)d_in[1];
    const float* w    = (const float*)d_in[2];
    const float* bias = (const float*)d_in[3];
    float* out = (float*)d_out;

    const long long T = (long long)in_sizes[0] / DK;

    const long long nA4 = T * DK / 4;
    const long long nW4 = (long long)E_NUM * DN * DK / 4;
    cvt_all_kernel<<<4736, 256>>>((const float4*)w, (const float4*)x, nW4, nA4);
    build_tiles_kernel<<<1, 32>>>(ef, (int)T);

    cudaFuncSetAttribute(gemm_kernel, cudaFuncAttributeMaxDynamicSharedMemorySize, SMEM_TOTAL);

    const int mt_max = (int)((T + BM - 1) / BM) + E_NUM;   /* ~1056 */
    dim3 grid(DN / BN, (unsigned)mt_max);                  /* (8, ~1056) */
    gemm_kernel<<<grid, 256, SMEM_TOTAL>>>(bias, out, (int)T);
}

// round 6
// speedup vs baseline: 1.4114x; 1.0961x over previous
#include <cuda_runtime.h>
#include <cuda_fp16.h>
#include <cstdint>

#define E_NUM 32
#define DK 1024
#define DN 1024
#define BM 128
#define BN 128
#define KC 64            /* fp16 per K-chunk = 128 bytes/row */
#define NCHUNK (DK / KC) /* 16 */
#define STAGES 3
#define MT_CAP 1152
#define TMAX 131072LL

/* ---------------- scratch (device globals; no allocation APIs) -------------- */
static __device__ __align__(1024) __half g_Ah[TMAX * DK];                   /* 256 MB */
static __device__ __align__(1024) __half g_Wh[(long long)E_NUM * DN * DK];  /* 64 MB  */
static __device__ int g_tile_expert[MT_CAP];
static __device__ int g_tile_row[MT_CAP];
static __device__ int g_tile_nrows[MT_CAP];
static __device__ int g_num_mtiles;

/* ---------------- helpers ---------------- */
static __device__ __forceinline__ uint32_t smem_u32(const void* p) {
    uint32_t a;
    asm("{ .reg .u64 t; cvta.to.shared.u64 t, %1; cvt.u32.u64 %0, t; }" : "=r"(a) : "l"(p));
    return a;
}
static __device__ __forceinline__ void cp16(uint32_t dst, const void* src, int src_size) {
    asm volatile("cp.async.cg.shared.global [%0], [%1], 16, %2;\n"
                 :: "r"(dst), "l"(src), "r"(src_size));
}
/* async arrive on mbarrier when this thread's prior cp.asyncs complete */
static __device__ __forceinline__ void cp_async_arrive(uint32_t mbar) {
    asm volatile("cp.async.mbarrier.arrive.noinc.shared.b64 [%0];" :: "r"(mbar) : "memory");
}

#define MBARRIER_INIT(addr, cnt) \
    asm volatile("mbarrier.init.shared.b64 [%0], %1;" :: "r"((uint32_t)(addr)), "r"((uint32_t)(cnt)) : "memory")
#define MBARRIER_ARRIVE(addr) \
    asm volatile("mbarrier.arrive.shared.b64 _, [%0];" :: "r"((uint32_t)(addr)) : "memory")

#define MBARRIER_WAIT_PARITY(mbar_smem_addr, phase_parity) do {                                   \
    uint32_t _mbar = (uint32_t)(mbar_smem_addr);                                                  \
    uint32_t _parity = (uint32_t)(phase_parity);                                                  \
    uint32_t _done;                                                                               \
    asm volatile(                                                                                 \
        "{\n\t"                                                                                   \
        ".reg .pred p;\n\t"                                                                       \
        "mbarrier.try_wait.parity.acquire.cta.shared::cta.b64 p, [%1], %2;\n\t"                   \
        "selp.b32 %0, 1, 0, p;\n\t"                                                               \
        "}"                                                                                       \
        : "=r"(_done) : "r"(_mbar), "r"(_parity) : "memory");                                     \
    if (!_done) {                                                                                 \
        asm volatile(                                                                             \
            "{\n\t"                                                                               \
            ".reg .pred P1;\n\t"                                                                  \
            "WAIT_LOOP_%=:\n\t"                                                                   \
            "mbarrier.try_wait.parity.acquire.cta.shared::cta.b64 P1, [%0], %1, 0x989680;\n\t"    \
            "@P1 bra.uni WAIT_DONE_%=;\n\t"                                                       \
            "bra.uni WAIT_LOOP_%=;\n\t"                                                           \
            "WAIT_DONE_%=:\n\t"                                                                   \
            "}"                                                                                   \
            :: "r"(_mbar), "r"(_parity) : "memory");                                              \
    }                                                                                             \
} while (0)

#define LDSM_X4(r0, r1, r2, r3, addr) \
    asm volatile("ldmatrix.sync.aligned.m8n8.x4.shared.b16 {%0,%1,%2,%3}, [%4];" \
                 : "=r"(r0), "=r"(r1), "=r"(r2), "=r"(r3) : "r"(addr))

#define MMA16816(c0, c1, c2, c3, a0, a1, a2, a3, b0, b1) \
    asm volatile("mma.sync.aligned.m16n8k16.row.col.f32.f16.f16.f32 " \
                 "{%0,%1,%2,%3}, {%4,%5,%6,%7}, {%8,%9}, {%0,%1,%2,%3};" \
                 : "+f"(c0), "+f"(c1), "+f"(c2), "+f"(c3) \
                 : "r"(a0), "r"(a1), "r"(a2), "r"(a3), "r"(b0), "r"(b1))

/* ---------------- fused fp32->fp16 conversion (W then A, one launch) -------- */
__global__ void cvt_all_kernel(const float4* __restrict__ srcW,
                               const float4* __restrict__ srcA,
                               long long nW4, long long nA4) {
    long long i = (long long)blockIdx.x * blockDim.x + threadIdx.x;
    long long stride = (long long)gridDim.x * blockDim.x;
    uint2* dstW = reinterpret_cast<uint2*>(g_Wh);
    uint2* dstA = reinterpret_cast<uint2*>(g_Ah);
    const long long ntot = nW4 + nA4;
    for (; i < ntot; i += stride) {
        const bool isW = (i < nW4);
        const long long j = isW ? i : (i - nW4);
        float4 v = isW ? srcW[j] : srcA[j];
        __half2 h0 = __floats2half2_rn(v.x, v.y);
        __half2 h1 = __floats2half2_rn(v.z, v.w);
        uint2 u;
        u.x = *reinterpret_cast<uint32_t*>(&h0);
        u.y = *reinterpret_cast<uint32_t*>(&h1);
        if (isW) dstW[j] = u; else dstA[j] = u;
    }
}

/* Build tile table. Handles expert_frequency delivered as int32 OR int64. */
__global__ void build_tiles_kernel(const int* __restrict__ ef, int T_tokens) {
    if (threadIdx.x != 0 || blockIdx.x != 0) return;
    long long s = 0;
    for (int i = 0; i < E_NUM; i++) s += ef[i];
    bool is64 = (s != (long long)T_tokens);
    long long off = 0;
    int t = 0;
    for (int e = 0; e < E_NUM; e++) {
        long long c;
        if (is64)
            c = (long long)(unsigned)ef[2 * e] | ((long long)ef[2 * e + 1] << 32);
        else
            c = ef[e];
        for (long long m = 0; m < c; m += BM) {
            long long rem = c - m;
            g_tile_expert[t] = e;
            g_tile_row[t]    = (int)(off + m);
            g_tile_nrows[t]  = (int)(rem < BM ? rem : BM);
            t++;
        }
        off += c;
    }
    g_num_mtiles = t;
}

/* ---------------- main grouped-GEMM kernel (mma.sync fp16) ----------------
   R2 tile config (CTA 128x128, 8 warps 4m x 2n, warp 32x64, 2 CTAs/SM) but
   the CTA-wide __syncthreads/wait_group pipeline is replaced by per-stage
   mbarrier full/empty pairs:
     full[s]:  count 256, tripped by cp.async.mbarrier.arrive (per thread)
     empty[s]: count 8,   one release-arrive per warp after its LDSMs
   Consumers wait per-warp (try_wait.parity) so warps de-align and LDSM
   windows overlap other warps' MMA bursts.                                  */

#define STAGE_BYTES 32768              /* A 16KB + B 16KB */
#define MBAR_BYTES  1024
#define SMEM_TOTAL  (STAGES * STAGE_BYTES + MBAR_BYTES)
/* mbarrier region at offset STAGES*STAGE_BYTES: full[0..2] at +0,8,16; empty[0..2] at +32,40,48 */

static __device__ __forceinline__ void produce_chunk(
    int cc, uint32_t smem_base, uint32_t mbar_base,
    const __half* __restrict__ gA, const __half* __restrict__ gB,
    int a_sz, int tid, uint32_t* emptyph)
{
    const int s = cc % STAGES;
    if (cc >= STAGES) {   /* first use of each stage needs no empty-wait */
        MBARRIER_WAIT_PARITY(mbar_base + 32 + s * 8, (*emptyph >> s) & 1);
        *emptyph ^= (1u << s);
    }
    const int row  = tid >> 1;
    const int j0   = (tid & 1) * 4;
    const uint32_t xorv = (uint32_t)(row & 7) * 16u;
    uint32_t sA = smem_base + (uint32_t)s * STAGE_BYTES + (uint32_t)row * 128u;
    uint32_t sB = sA + 16384u;
    const char* srcA = (const char*)(gA + (size_t)row * DK + (size_t)cc * KC) + j0 * 16;
    const char* srcB = (const char*)(gB + (size_t)row * DK + (size_t)cc * KC) + j0 * 16;
#pragma unroll
    for (int j = 0; j < 4; j++) {
        uint32_t col = ((uint32_t)(j0 + j) * 16u) ^ xorv;
        cp16(sA + col, srcA + j * 16, a_sz);
        cp16(sB + col, srcB + j * 16, 16);
    }
    cp_async_arrive(mbar_base + s * 8);
}

__global__ void __launch_bounds__(256, 2) gemm_kernel(
    const float* __restrict__ bias, float* __restrict__ out, int T_tokens)
{
    extern __shared__ __align__(1024) char smem[];
    const int nt = blockIdx.x;           /* fast dim: 8 N-tiles co-resident for A reuse in L2 */
    const int mt = blockIdx.y;
    if (mt >= g_num_mtiles) return;

    const int e     = g_tile_expert[mt];
    const int row0  = g_tile_row[mt];
    const int nrows = g_tile_nrows[mt];

    const uint32_t smem_base = smem_u32(smem);
    const uint32_t mbar_base = smem_base + STAGES * STAGE_BYTES;
    const int tid  = threadIdx.x;
    const int lane = tid & 31;
    const int wid  = tid >> 5;
    const int warp_m = wid >> 1;         /* 0..3 */
    const int warp_n = wid & 1;          /* 0..1 */

    if (tid == 0) {
#pragma unroll
        for (int s = 0; s < STAGES; s++) {
            MBARRIER_INIT(mbar_base + s * 8, 256);       /* full */
            MBARRIER_INIT(mbar_base + 32 + s * 8, 8);    /* empty */
        }
    }
    __syncthreads();

    /* global load setup */
    const int arow = tid >> 1;
    const int a_sz = (row0 + arow < T_tokens) ? 16 : 0;
    const __half* gA = g_Ah + (size_t)row0 * DK;
    const __half* gB = g_Wh + ((size_t)e * DN + (size_t)nt * BN) * DK;

    /* ldmatrix per-lane address components */
    uint32_t aRow[2], aXor[2];
#pragma unroll
    for (int mf = 0; mf < 2; mf++) {
        int r = warp_m * 32 + mf * 16 + (lane & 15);
        aRow[mf] = (uint32_t)r * 128u;
        aXor[mf] = (uint32_t)(r & 7) * 16u;
    }
    const uint32_t aHi = (uint32_t)((lane >> 4) & 1) * 16u;

    uint32_t bRow[4], bXor[4];
#pragma unroll
    for (int g = 0; g < 4; g++) {
        int r = warp_n * 64 + g * 16 + (lane & 7) + (((lane >> 4) & 1) << 3);
        bRow[g] = (uint32_t)r * 128u;
        bXor[g] = (uint32_t)(r & 7) * 16u;
    }
    const uint32_t bHi = (uint32_t)((lane >> 3) & 1) * 16u;

    float acc[2][8][4];
#pragma unroll
    for (int mf = 0; mf < 2; mf++)
#pragma unroll
        for (int nf = 0; nf < 8; nf++)
#pragma unroll
            for (int k = 0; k < 4; k++) acc[mf][nf][k] = 0.0f;

    uint32_t fullph = 0, emptyph = 0;

    /* prologue: chunks 0 and 1 (no waits: first use of stages 0,1) */
    produce_chunk(0, smem_base, mbar_base, gA, gB, a_sz, tid, &emptyph);
    produce_chunk(1, smem_base, mbar_base, gA, gB, a_sz, tid, &emptyph);

#pragma unroll 1
    for (int c = 0; c < NCHUNK; c++) {
        const int s = c % STAGES;

        /* produce chunk c+2 (its stage was consumed at chunk c-1) */
        if (c + 2 < NCHUNK)
            produce_chunk(c + 2, smem_base, mbar_base, gA, gB, a_sz, tid, &emptyph);

        /* consume chunk c: per-warp wait on full[s] */
        MBARRIER_WAIT_PARITY(mbar_base + s * 8, (fullph >> s) & 1);
        fullph ^= (1u << s);

        const uint32_t sA = smem_base + (uint32_t)s * STAGE_BYTES;
        const uint32_t sB = sA + 16384u;

#pragma unroll
        for (int ks = 0; ks < 4; ks++) {
            const uint32_t kb = (uint32_t)ks * 32u;
            uint32_t a[2][4];
#pragma unroll
            for (int mf = 0; mf < 2; mf++) {
                uint32_t addr = sA + aRow[mf] + ((kb + aHi) ^ aXor[mf]);
                LDSM_X4(a[mf][0], a[mf][1], a[mf][2], a[mf][3], addr);
            }
            uint32_t b[4][4];
#pragma unroll
            for (int g = 0; g < 4; g++) {
                uint32_t addr = sB + bRow[g] + ((kb + bHi) ^ bXor[g]);
                LDSM_X4(b[g][0], b[g][1], b[g][2], b[g][3], addr);
            }
#pragma unroll
            for (int mf = 0; mf < 2; mf++) {
#pragma unroll
                for (int nf = 0; nf < 8; nf++) {
                    const int g  = nf >> 1;
                    const int hi = (nf & 1) * 2;
                    MMA16816(acc[mf][nf][0], acc[mf][nf][1], acc[mf][nf][2], acc[mf][nf][3],
                             a[mf][0], a[mf][1], a[mf][2], a[mf][3],
                             b[g][hi], b[g][hi + 1]);
                }
            }
        }

        /* this warp is done reading stage s (all LDSMs issued & consumed) */
        if (lane == 0) MBARRIER_ARRIVE(mbar_base + 32 + s * 8);
    }

    /* epilogue: out = acc + bias (no final sync needed; acc is private) */
    const int colBase = nt * BN + warp_n * 64 + (lane & 3) * 2;
    const float* brow = bias + (size_t)e * DN;
#pragma unroll
    for (int mf = 0; mf < 2; mf++) {
#pragma unroll
        for (int half = 0; half < 2; half++) {
            const int r = warp_m * 32 + mf * 16 + (lane >> 2) + half * 8;
            if (r < nrows) {
                float* orow = out + (size_t)(row0 + r) * DN;
#pragma unroll
                for (int nf = 0; nf < 8; nf++) {
                    const int col = colBase + nf * 8;
                    float2 v;
                    v.x = acc[mf][nf][half * 2 + 0] + brow[col];
                    v.y = acc[mf][nf][half * 2 + 1] + brow[col + 1];
                    *(float2*)(orow + col) = v;
                }
            }
        }
    }
}

/* ---------------- host launcher ---------------- */
extern "C" void kernel_launch(void* const* d_in, const int* in_sizes, int n_in,
                              void* d_out, int out_size)
{
    const float* x    = (const float*)d_in[0];
    const int*   ef   = (const int*)d_in[1];
    const float* w    = (const float*)d_in[2];
    const float* bias = (const float*)d_in[3];
    float* out = (float*)d_out;

    const long long T = (long long)in_sizes[0] / DK;

    const long long nA4 = T * DK / 4;
    const long long nW4 = (long long)E_NUM * DN * DK / 4;
    cvt_all_kernel<<<4736, 256>>>((const float4*)w, (const float4*)x, nW4, nA4);
    build_tiles_kernel<<<1, 32>>>(ef, (int)T);

    cudaFuncSetAttribute(gemm_kernel, cudaFuncAttributeMaxDynamicSharedMemorySize, SMEM_TOTAL);

    const int mt_max = (int)((T + BM - 1) / BM) + E_NUM;   /* ~1056 */
    dim3 grid(DN / BN, (unsigned)mt_max);                  /* (8, ~1056) */
    gemm_kernel<<<grid, 256, SMEM_TOTAL>>>(bias, out, (int)T);
}